// round 5
// baseline (speedup 1.0000x reference)
#include <cuda_runtime.h>
#include <cuda_bf16.h>

#define NX 2048
#define NY 4096
#define FULLMASK 0xffffffffu

// kind: 0 = left one-sided, 1 = centered, 2 = right one-sided
__device__ __forceinline__ void stencil_coeffs(float g0, float g1, float g2, int kind,
                                               float c1[3], float c2[3]) {
    float ha = g1 - g0;
    float hb = g2 - g1;
    float sab = ha + hb;
    float inv = 1.0f / (ha * hb * sab);
    float i_a  = hb  * inv;   // 1/(ha*(ha+hb))
    float i_ab = sab * inv;   // 1/(ha*hb)
    float i_b  = ha  * inv;   // 1/(hb*(ha+hb))
    c2[0] = 2.0f * i_a;
    c2[1] = -2.0f * i_ab;
    c2[2] = 2.0f * i_b;
    if (kind == 0) {
        c1[0] = -(2.0f * ha + hb) * i_a;
        c1[1] = sab * i_ab;
        c1[2] = -ha * i_b;
    } else if (kind == 2) {
        c1[0] = hb * i_a;
        c1[1] = -sab * i_ab;
        c1[2] = (ha + 2.0f * hb) * i_b;
    } else {
        c1[0] = -hb * i_a;
        c1[1] = (hb - ha) * i_ab;
        c1[2] = ha * i_b;
    }
}

// Block = 32x4 threads. Covers 128 j (32 lanes x 4) by 16 i (4 ty x 4).
// Coefficients computed once per block into smem.
__global__ __launch_bounds__(128, 4) void rhs_kernel(const float* __restrict__ state,
                                                     const float* __restrict__ xg,
                                                     const float* __restrict__ yg,
                                                     const float* __restrict__ mu_p,
                                                     float* __restrict__ out) {
    __shared__ float yc[6][128];   // c1y[0..2], c2y[0..2] per local j
    __shared__ float xc[6][16];    // c1x[0..2], c2x[0..2] per local i

    const int lane = threadIdx.x;                 // 0..31
    const int ty   = threadIdx.y;                 // 0..3
    const int t    = ty * 32 + lane;              // 0..127
    const int jblk = blockIdx.x * 128;            // block's first j
    const int iblk = blockIdx.y * 16;             // block's first i
    const int j0 = jblk + lane * 4;
    const int i0 = iblk + ty * 4;

    // ---- fill coefficient smem ----
    {
        int jj = jblk + t;
        int s = min(max(jj - 1, 0), NY - 3);
        int kind = (jj == 0) ? 0 : ((jj == NY - 1) ? 2 : 1);
        float c1[3], c2[3];
        stencil_coeffs(yg[s], yg[s + 1], yg[s + 2], kind, c1, c2);
        yc[0][t] = c1[0]; yc[1][t] = c1[1]; yc[2][t] = c1[2];
        yc[3][t] = c2[0]; yc[4][t] = c2[1]; yc[5][t] = c2[2];
    }
    if (t < 16) {
        int ii = iblk + t;
        int s = min(max(ii - 1, 0), NX - 3);
        int kind = (ii == 0) ? 0 : ((ii == NX - 1) ? 2 : 1);
        float c1[3], c2[3];
        stencil_coeffs(xg[s], xg[s + 1], xg[s + 2], kind, c1, c2);
        xc[0][t] = c1[0]; xc[1][t] = c1[1]; xc[2][t] = c1[2];
        xc[3][t] = c2[0]; xc[4][t] = c2[1]; xc[5][t] = c2[2];
    }
    __syncthreads();

    const float* __restrict__ u = state;
    const float* __restrict__ v = state + NX * NY;

    // ---- load 6 state rows per field: rows clamp(i0-1 .. i0+4), 32-bit offsets ----
    float4 U[6], V[6];
#pragma unroll
    for (int k = 0; k < 6; k++) {
        int r = min(max(i0 - 1 + k, 0), NX - 1);
        int off = r * NY + j0;
        U[k] = *(const float4*)(u + off);
        V[k] = *(const float4*)(v + off);
    }

    // Warp-edge scalar neighbors (only lanes 0 / 31 actually load)
    float uLe[4], uRe[4], vLe[4], vRe[4];
    const bool haveL = (lane == 0) && (j0 > 0);
    const bool haveR = (lane == 31) && (j0 + 4 < NY);
#pragma unroll
    for (int m = 0; m < 4; m++) {
        int off = (i0 + m) * NY + j0;
        uLe[m] = haveL ? u[off - 1] : 0.0f;
        vLe[m] = haveL ? v[off - 1] : 0.0f;
        uRe[m] = haveR ? u[off + 4] : 0.0f;
        vRe[m] = haveR ? v[off + 4] : 0.0f;
    }

    // ---- read this thread's y coefficients (float4, conflict-free) ----
    const int lj = lane * 4;
    const float4 c1y0 = *(const float4*)&yc[0][lj];
    const float4 c1y1 = *(const float4*)&yc[1][lj];
    const float4 c1y2 = *(const float4*)&yc[2][lj];
    const float4 c2y0 = *(const float4*)&yc[3][lj];
    const float4 c2y1 = *(const float4*)&yc[4][lj];
    const float4 c2y2 = *(const float4*)&yc[5][lj];
    const float C1Y0[4] = {c1y0.x, c1y0.y, c1y0.z, c1y0.w};
    const float C1Y1[4] = {c1y1.x, c1y1.y, c1y1.z, c1y1.w};
    const float C1Y2[4] = {c1y2.x, c1y2.y, c1y2.z, c1y2.w};
    const float C2Y0[4] = {c2y0.x, c2y0.y, c2y0.z, c2y0.w};
    const float C2Y1[4] = {c2y1.x, c2y1.y, c2y1.z, c2y1.w};
    const float C2Y2[4] = {c2y2.x, c2y2.y, c2y2.z, c2y2.w};

    const bool eL = (j0 == 0);
    const bool eR = (j0 == NY - 4);
    const bool firstB = (i0 == 0);
    const bool lastB = (i0 == NX - 4);
    const float mu = mu_p[0];

#pragma unroll
    for (int m = 0; m < 4; m++) {
        const int i = i0 + m;
        const int li = ty * 4 + m;

        // x coefficients (warp-uniform smem broadcast)
        const float cx10 = xc[0][li], cx11 = xc[1][li], cx12 = xc[2][li];
        const float cx20 = xc[3][li], cx21 = xc[4][li], cx22 = xc[5][li];

        // select x-stencil data rows
        float4 u0, u1, u2, v0, v1, v2;
        if (m == 0) {
            u0 = firstB ? U[1] : U[0]; u1 = firstB ? U[2] : U[1]; u2 = firstB ? U[3] : U[2];
            v0 = firstB ? V[1] : V[0]; v1 = firstB ? V[2] : V[1]; v2 = firstB ? V[3] : V[2];
        } else if (m == 3) {
            u0 = lastB ? U[2] : U[3]; u1 = lastB ? U[3] : U[4]; u2 = lastB ? U[4] : U[5];
            v0 = lastB ? V[2] : V[3]; v1 = lastB ? V[3] : V[4]; v2 = lastB ? V[4] : V[5];
        } else {
            u0 = U[m]; u1 = U[m + 1]; u2 = U[m + 2];
            v0 = V[m]; v1 = V[m + 1]; v2 = V[m + 2];
        }

        // center row (global row i) is always U[m+1] / V[m+1]
        const float4 uc = U[m + 1];
        const float4 vc = V[m + 1];

        // y-neighbors via warp shuffle, patched at warp edges
        float uLm = __shfl_up_sync(FULLMASK, uc.w, 1);
        float vLm = __shfl_up_sync(FULLMASK, vc.w, 1);
        float uRm = __shfl_down_sync(FULLMASK, uc.x, 1);
        float vRm = __shfl_down_sync(FULLMASK, vc.x, 1);
        if (lane == 0)  { uLm = uLe[m]; vLm = vLe[m]; }
        if (lane == 31) { uRm = uRe[m]; vRm = vRe[m]; }

        const float u_vals[6] = {uLm, uc.x, uc.y, uc.z, uc.w, uRm};
        const float v_vals[6] = {vLm, vc.x, vc.y, vc.z, vc.w, vRm};
        const float AX0[4] = {u0.x, u0.y, u0.z, u0.w};
        const float AX1[4] = {u1.x, u1.y, u1.z, u1.w};
        const float AX2[4] = {u2.x, u2.y, u2.z, u2.w};
        const float BX0[4] = {v0.x, v0.y, v0.z, v0.w};
        const float BX1[4] = {v1.x, v1.y, v1.z, v1.w};
        const float BX2[4] = {v2.x, v2.y, v2.z, v2.w};

        float du[4], dv[4];
#pragma unroll
        for (int l = 0; l < 4; l++) {
            float f0 = u_vals[l], f1 = u_vals[l + 1], f2 = u_vals[l + 2];
            float g0 = v_vals[l], g1 = v_vals[l + 1], g2 = v_vals[l + 2];
            if (eL && l == 0) {         // one-sided at j=0: data points 0,1,2
                f0 = u_vals[1]; f1 = u_vals[2]; f2 = u_vals[3];
                g0 = v_vals[1]; g1 = v_vals[2]; g2 = v_vals[3];
            }
            if (eR && l == 3) {         // one-sided at j=NY-1: data NY-3..NY-1
                f0 = u_vals[2]; f1 = u_vals[3]; f2 = u_vals[4];
                g0 = v_vals[2]; g1 = v_vals[3]; g2 = v_vals[4];
            }

            float d1yu = C1Y0[l] * f0 + C1Y1[l] * f1 + C1Y2[l] * f2;
            float d2yu = C2Y0[l] * f0 + C2Y1[l] * f1 + C2Y2[l] * f2;
            float d1yv = C1Y0[l] * g0 + C1Y1[l] * g1 + C1Y2[l] * g2;
            float d2yv = C2Y0[l] * g0 + C2Y1[l] * g1 + C2Y2[l] * g2;

            float d1xu = cx10 * AX0[l] + cx11 * AX1[l] + cx12 * AX2[l];
            float d2xu = cx20 * AX0[l] + cx21 * AX1[l] + cx22 * AX2[l];
            float d1xv = cx10 * BX0[l] + cx11 * BX1[l] + cx12 * BX2[l];
            float d2xv = cx20 * BX0[l] + cx21 * BX1[l] + cx22 * BX2[l];

            float ucen = u_vals[l + 1];
            float vcen = v_vals[l + 1];

            du[l] = mu * (d2yu + d2xu) - ucen * d1xu - vcen * d1yu + 0.01f;
            dv[l] = mu * (d2yv + d2xv) - ucen * d1xv - vcen * d1yv;

            int jj = j0 + l;
            if (jj == 0 || i == 0) { du[l] = 0.0f; dv[l] = 0.0f; }
            if (jj == NY - 1) du[l] = 0.0f;
        }

        int off = i * NY + j0;
        *(float4*)(out + off) = make_float4(du[0], du[1], du[2], du[3]);
        *(float4*)(out + NX * NY + off) = make_float4(dv[0], dv[1], dv[2], dv[3]);
    }
}

extern "C" void kernel_launch(void* const* d_in, const int* in_sizes, int n_in,
                              void* d_out, int out_size) {
    // inputs: 0=t(1), 1=state(2*NX*NY), 2=x(NX), 3=y(NY), 4=mu(1)
    const float* x_g   = (const float*)d_in[2];
    const float* y_g   = (const float*)d_in[3];
    const float* state = (const float*)d_in[1];
    const float* mu    = (const float*)d_in[4];
    float* out = (float*)d_out;

    dim3 blk(32, 4);                 // 128 threads
    dim3 grd(NY / 128, NX / 16);     // (32, 128)
    rhs_kernel<<<grd, blk>>>(state, x_g, y_g, mu, out);
}

// round 6
// speedup vs baseline: 1.0501x; 1.0501x over previous
#include <cuda_runtime.h>
#include <cuda_bf16.h>

#define NX 2048
#define NY 4096
#define FULLMASK 0xffffffffu

// Build c1/c2 from precomputed ha, hb and inv = 1/(ha*hb*(ha+hb)).
// kind: 0 = left one-sided, 1 = centered, 2 = right one-sided
__device__ __forceinline__ void coeffs_from_inv(float ha, float hb, float inv, int kind,
                                                float c1[3], float c2[3]) {
    float sab = ha + hb;
    float i_a  = hb  * inv;   // 1/(ha*(ha+hb))
    float i_ab = sab * inv;   // 1/(ha*hb)
    float i_b  = ha  * inv;   // 1/(hb*(ha+hb))
    c2[0] = 2.0f * i_a;
    c2[1] = -2.0f * i_ab;
    c2[2] = 2.0f * i_b;
    if (kind == 0) {
        c1[0] = -(2.0f * ha + hb) * i_a;
        c1[1] = sab * i_ab;
        c1[2] = -ha * i_b;
    } else if (kind == 2) {
        c1[0] = hb * i_a;
        c1[1] = -sab * i_ab;
        c1[2] = (ha + 2.0f * hb) * i_b;
    } else {
        c1[0] = -hb * i_a;
        c1[1] = (hb - ha) * i_ab;
        c1[2] = ha * i_b;
    }
}

// Each thread: 4 consecutive j (float4) x 4 consecutive i rows.
__global__ __launch_bounds__(128, 4) void rhs_kernel(const float* __restrict__ state,
                                                     const float* __restrict__ xg,
                                                     const float* __restrict__ yg,
                                                     const float* __restrict__ mu_p,
                                                     float* __restrict__ out) {
    const int lane = threadIdx.x;                       // 0..31
    const int jg = blockIdx.x * 32 + lane;              // j-group
    const int j0 = jg * 4;
    const int it = blockIdx.y * blockDim.y + threadIdx.y;
    const int i0 = it * 4;

    const float* __restrict__ u = state;
    const float* __restrict__ v = state + NX * NY;

    // ---- load 6 state rows per field: rows clamp(i0-1 .. i0+4) ----
    float4 U[6], V[6];
#pragma unroll
    for (int k = 0; k < 6; k++) {
        int r = min(max(i0 - 1 + k, 0), NX - 1);
        int off = r * NY + j0;
        U[k] = *(const float4*)(u + off);
        V[k] = *(const float4*)(v + off);
    }

    // y grid points for this thread's 4 j positions
    float ys[6];
#pragma unroll
    for (int t = 0; t < 6; t++)
        ys[t] = yg[min(max(j0 - 1 + t, 0), NY - 1)];

    // Warp-edge scalar neighbors (only lanes 0 / 31 actually load)
    float uLe[4], uRe[4], vLe[4], vRe[4];
    const bool haveL = (lane == 0) && (j0 > 0);
    const bool haveR = (lane == 31) && (j0 + 4 < NY);
#pragma unroll
    for (int m = 0; m < 4; m++) {
        int off = (i0 + m) * NY + j0;
        uLe[m] = haveL ? u[off - 1] : 0.0f;
        vLe[m] = haveL ? v[off - 1] : 0.0f;
        uRe[m] = haveR ? u[off + 4] : 0.0f;
        vRe[m] = haveR ? v[off + 4] : 0.0f;
    }

    const bool eL = (j0 == 0);
    const bool eR = (j0 == NY - 4);
    const bool firstB = (i0 == 0);
    const bool lastB = (i0 == NX - 4);

    // ---- x coefficients: each lane computes ONE row's set (row = lane&3), 1 RCP ----
    float cx1p[3], cx2p[3];
    {
        int mx = lane & 3;
        int ii = i0 + mx;
        int s = min(max(ii - 1, 0), NX - 3);
        int kind = (ii == 0) ? 0 : ((ii == NX - 1) ? 2 : 1);
        float g0 = xg[s], g1 = xg[s + 1], g2 = xg[s + 2];
        float ha = g1 - g0, hb = g2 - g1;
        float inv = 1.0f / (ha * hb * (ha + hb));
        coeffs_from_inv(ha, hb, inv, kind, cx1p, cx2p);
    }

    // ---- y coefficients: 4 sets with pair-batched reciprocals (2 RCPs) ----
    float C1Y0[4], C1Y1[4], C1Y2[4], C2Y0[4], C2Y1[4], C2Y2[4];
    {
        float HA[4], HB[4], T[4];
        int KND[4];
#pragma unroll
        for (int l = 0; l < 4; l++) {
            float g0 = ys[l], g1 = ys[l + 1], g2 = ys[l + 2];
            int kind = 1;
            if (l == 0 && eL) { g0 = ys[1]; g1 = ys[2]; g2 = ys[3]; kind = 0; }
            if (l == 3 && eR) { g0 = ys[2]; g1 = ys[3]; g2 = ys[4]; kind = 2; }
            HA[l] = g1 - g0;
            HB[l] = g2 - g1;
            T[l] = HA[l] * HB[l] * (HA[l] + HB[l]);
            KND[l] = kind;
        }
        float ip01 = 1.0f / (T[0] * T[1]);
        float ip23 = 1.0f / (T[2] * T[3]);
        float INV[4] = {ip01 * T[1], ip01 * T[0], ip23 * T[3], ip23 * T[2]};
#pragma unroll
        for (int l = 0; l < 4; l++) {
            float c1[3], c2[3];
            coeffs_from_inv(HA[l], HB[l], INV[l], KND[l], c1, c2);
            C1Y0[l] = c1[0]; C1Y1[l] = c1[1]; C1Y2[l] = c1[2];
            C2Y0[l] = c2[0]; C2Y1[l] = c2[1]; C2Y2[l] = c2[2];
        }
    }

    const float mu = mu_p[0];

#pragma unroll
    for (int m = 0; m < 4; m++) {
        const int i = i0 + m;

        // x coefficients for this row: broadcast from lane (quad-local) m
        const float cx10 = __shfl_sync(FULLMASK, cx1p[0], m, 4);
        const float cx11 = __shfl_sync(FULLMASK, cx1p[1], m, 4);
        const float cx12 = __shfl_sync(FULLMASK, cx1p[2], m, 4);
        const float cx20 = __shfl_sync(FULLMASK, cx2p[0], m, 4);
        const float cx21 = __shfl_sync(FULLMASK, cx2p[1], m, 4);
        const float cx22 = __shfl_sync(FULLMASK, cx2p[2], m, 4);

        // select x-stencil data rows
        float4 u0, u1, u2, v0, v1, v2;
        if (m == 0) {
            u0 = firstB ? U[1] : U[0]; u1 = firstB ? U[2] : U[1]; u2 = firstB ? U[3] : U[2];
            v0 = firstB ? V[1] : V[0]; v1 = firstB ? V[2] : V[1]; v2 = firstB ? V[3] : V[2];
        } else if (m == 3) {
            u0 = lastB ? U[2] : U[3]; u1 = lastB ? U[3] : U[4]; u2 = lastB ? U[4] : U[5];
            v0 = lastB ? V[2] : V[3]; v1 = lastB ? V[3] : V[4]; v2 = lastB ? V[4] : V[5];
        } else {
            u0 = U[m]; u1 = U[m + 1]; u2 = U[m + 2];
            v0 = V[m]; v1 = V[m + 1]; v2 = V[m + 2];
        }

        // center row (global row i) is always U[m+1] / V[m+1]
        const float4 uc = U[m + 1];
        const float4 vc = V[m + 1];

        // y-neighbors via warp shuffle, patched at warp edges
        float uLm = __shfl_up_sync(FULLMASK, uc.w, 1);
        float vLm = __shfl_up_sync(FULLMASK, vc.w, 1);
        float uRm = __shfl_down_sync(FULLMASK, uc.x, 1);
        float vRm = __shfl_down_sync(FULLMASK, vc.x, 1);
        if (lane == 0)  { uLm = uLe[m]; vLm = vLe[m]; }
        if (lane == 31) { uRm = uRe[m]; vRm = vRe[m]; }

        const float u_vals[6] = {uLm, uc.x, uc.y, uc.z, uc.w, uRm};
        const float v_vals[6] = {vLm, vc.x, vc.y, vc.z, vc.w, vRm};
        const float AX0[4] = {u0.x, u0.y, u0.z, u0.w};
        const float AX1[4] = {u1.x, u1.y, u1.z, u1.w};
        const float AX2[4] = {u2.x, u2.y, u2.z, u2.w};
        const float BX0[4] = {v0.x, v0.y, v0.z, v0.w};
        const float BX1[4] = {v1.x, v1.y, v1.z, v1.w};
        const float BX2[4] = {v2.x, v2.y, v2.z, v2.w};

        float du[4], dv[4];
#pragma unroll
        for (int l = 0; l < 4; l++) {
            float f0 = u_vals[l], f1 = u_vals[l + 1], f2 = u_vals[l + 2];
            float g0 = v_vals[l], g1 = v_vals[l + 1], g2 = v_vals[l + 2];
            if (eL && l == 0) {         // one-sided at j=0: data points 0,1,2
                f0 = u_vals[1]; f1 = u_vals[2]; f2 = u_vals[3];
                g0 = v_vals[1]; g1 = v_vals[2]; g2 = v_vals[3];
            }
            if (eR && l == 3) {         // one-sided at j=NY-1: data NY-3..NY-1
                f0 = u_vals[2]; f1 = u_vals[3]; f2 = u_vals[4];
                g0 = v_vals[2]; g1 = v_vals[3]; g2 = v_vals[4];
            }

            float d1yu = C1Y0[l] * f0 + C1Y1[l] * f1 + C1Y2[l] * f2;
            float d2yu = C2Y0[l] * f0 + C2Y1[l] * f1 + C2Y2[l] * f2;
            float d1yv = C1Y0[l] * g0 + C1Y1[l] * g1 + C1Y2[l] * g2;
            float d2yv = C2Y0[l] * g0 + C2Y1[l] * g1 + C2Y2[l] * g2;

            float d1xu = cx10 * AX0[l] + cx11 * AX1[l] + cx12 * AX2[l];
            float d2xu = cx20 * AX0[l] + cx21 * AX1[l] + cx22 * AX2[l];
            float d1xv = cx10 * BX0[l] + cx11 * BX1[l] + cx12 * BX2[l];
            float d2xv = cx20 * BX0[l] + cx21 * BX1[l] + cx22 * BX2[l];

            float ucen = u_vals[l + 1];
            float vcen = v_vals[l + 1];

            du[l] = mu * (d2yu + d2xu) - ucen * d1xu - vcen * d1yu + 0.01f;
            dv[l] = mu * (d2yv + d2xv) - ucen * d1xv - vcen * d1yv;

            int jj = j0 + l;
            if (jj == 0 || i == 0) { du[l] = 0.0f; dv[l] = 0.0f; }
            if (jj == NY - 1) du[l] = 0.0f;
        }

        int off = i * NY + j0;
        *(float4*)(out + off) = make_float4(du[0], du[1], du[2], du[3]);
        *(float4*)(out + NX * NY + off) = make_float4(dv[0], dv[1], dv[2], dv[3]);
    }
}

extern "C" void kernel_launch(void* const* d_in, const int* in_sizes, int n_in,
                              void* d_out, int out_size) {
    // inputs: 0=t(1), 1=state(2*NX*NY), 2=x(NX), 3=y(NY), 4=mu(1)
    const float* x_g   = (const float*)d_in[2];
    const float* y_g   = (const float*)d_in[3];
    const float* state = (const float*)d_in[1];
    const float* mu    = (const float*)d_in[4];
    float* out = (float*)d_out;

    dim3 blk(32, 4);                       // 128 threads
    dim3 grd((NY / 4) / 32, NX / (4 * 4)); // (32, 128)
    rhs_kernel<<<grd, blk>>>(state, x_g, y_g, mu, out);
}